// round 1
// baseline (speedup 1.0000x reference)
#include <cuda_runtime.h>
#include <math.h>

// Problem dims
#define NB 8
#define NH 8
#define SLQ 1024
#define SLK 1024
#define DD 512
#define HD (NH*DD)   // 4096

// GEMM tile
#define BM 128
#define BN 128
#define BK 8
#define NTHREADS 256

// Scratch (device globals; no allocation allowed in kernel_launch)
__device__ float g_Q[(size_t)NB*NH*SLQ*DD];
__device__ float g_K[(size_t)NB*NH*SLK*DD];
__device__ float g_V[(size_t)NB*NH*SLK*DD];
__device__ float g_S[(size_t)NB*NH*SLQ*SLK];
__device__ float g_C[(size_t)NB*SLQ*HD];

struct Smem {
    float As[BK][BM];
    float Bs[BK][BN];
};

// Core 128x128 tile GEMM: C += A[M,K] * B^T (B_KMAJOR: B is [N,K] row-major)
// or C += A[M,K] * B (B is [K,N] row-major) when !B_KMAJOR.
// Caller pre-offsets A to its m0 row and B to its n0 row/col.
template<bool B_KMAJOR>
__device__ __forceinline__ void gemm_tile(
    const float* __restrict__ A, const float* __restrict__ Bp,
    int K, int lda, int ldb, float acc[8][8], Smem& s)
{
    const int tid  = threadIdx.x;
    const int arow = tid >> 1;          // 0..127
    const int acol = (tid & 1) << 2;    // 0 or 4
    const int bkr  = tid >> 5;          // 0..7   (NN layout)
    const int bnc  = (tid & 31) << 2;   // 0..124 (NN layout)
    const int ty   = tid >> 4;
    const int tx   = tid & 15;

    for (int kt = 0; kt < K; kt += BK) {
        // A tile: [BM x BK], k-contiguous, transpose into As[k][m]
        float4 a4 = *reinterpret_cast<const float4*>(A + (size_t)arow * lda + kt + acol);
        s.As[acol+0][arow] = a4.x;
        s.As[acol+1][arow] = a4.y;
        s.As[acol+2][arow] = a4.z;
        s.As[acol+3][arow] = a4.w;
        if (B_KMAJOR) {
            float4 b4 = *reinterpret_cast<const float4*>(Bp + (size_t)arow * ldb + kt + acol);
            s.Bs[acol+0][arow] = b4.x;
            s.Bs[acol+1][arow] = b4.y;
            s.Bs[acol+2][arow] = b4.z;
            s.Bs[acol+3][arow] = b4.w;
        } else {
            float4 b4 = *reinterpret_cast<const float4*>(Bp + (size_t)(kt + bkr) * ldb + bnc);
            *reinterpret_cast<float4*>(&s.Bs[bkr][bnc]) = b4;
        }
        __syncthreads();
        #pragma unroll
        for (int kk = 0; kk < BK; kk++) {
            float ra[8], rb[8];
            *(float4*)&ra[0] = *(const float4*)&s.As[kk][ty*8];
            *(float4*)&ra[4] = *(const float4*)&s.As[kk][ty*8+4];
            *(float4*)&rb[0] = *(const float4*)&s.Bs[kk][tx*8];
            *(float4*)&rb[4] = *(const float4*)&s.Bs[kk][tx*8+4];
            #pragma unroll
            for (int i = 0; i < 8; i++) {
                #pragma unroll
                for (int j = 0; j < 8; j++) {
                    acc[i][j] = fmaf(ra[i], rb[j], acc[i][j]);
                }
            }
        }
        __syncthreads();
    }
}

// -------- Stage 1: Q/K/V projections: y = x @ W_h^T + b_h --------
__global__ __launch_bounds__(NTHREADS) void qkv_kernel(
    const float* __restrict__ x, const float* __restrict__ states,
    const float* __restrict__ Wq, const float* __restrict__ Wk, const float* __restrict__ Wv,
    const float* __restrict__ bq, const float* __restrict__ bk, const float* __restrict__ bv)
{
    __shared__ Smem s;
    const int z = blockIdx.z;          // 0..191
    const int which = z >> 6;          // 0=q,1=k,2=v
    const int bh = z & 63;
    const int b = bh >> 3, h = bh & 7;

    const float* A    = (which == 0 ? x : states) + (size_t)b * SLQ * DD;
    const float* W    = (which == 0 ? Wq : (which == 1 ? Wk : Wv)) + (size_t)h * DD * DD;
    const float* bias = (which == 0 ? bq : (which == 1 ? bk : bv)) + h * DD;
    float* C          = (which == 0 ? g_Q : (which == 1 ? g_K : g_V)) + (size_t)bh * SLQ * DD;

    const int m0 = blockIdx.y * BM, n0 = blockIdx.x * BN;
    float acc[8][8] = {};
    gemm_tile<true>(A + (size_t)m0 * DD, W + (size_t)n0 * DD, DD, DD, DD, acc, s);

    const int ty = threadIdx.x >> 4, tx = threadIdx.x & 15;
    float bj[8];
    *(float4*)&bj[0] = *(const float4*)&bias[n0 + tx*8];
    *(float4*)&bj[4] = *(const float4*)&bias[n0 + tx*8 + 4];
    #pragma unroll
    for (int i = 0; i < 8; i++) {
        const size_t off = (size_t)(m0 + ty*8 + i) * DD + n0 + tx*8;
        float4 o0, o1;
        o0.x = acc[i][0] + bj[0]; o0.y = acc[i][1] + bj[1];
        o0.z = acc[i][2] + bj[2]; o0.w = acc[i][3] + bj[3];
        o1.x = acc[i][4] + bj[4]; o1.y = acc[i][5] + bj[5];
        o1.z = acc[i][6] + bj[6]; o1.w = acc[i][7] + bj[7];
        *(float4*)&C[off]     = o0;
        *(float4*)&C[off + 4] = o1;
    }
}

// -------- Stage 2: scores = (Q K^T) * scale, masked --------
__global__ __launch_bounds__(NTHREADS) void scores_kernel(const int* __restrict__ mask)
{
    __shared__ Smem s;
    const int bh = blockIdx.z;
    const int b = bh >> 3;
    const float* Q  = g_Q + (size_t)bh * SLQ * DD;
    const float* Kp = g_K + (size_t)bh * SLK * DD;
    float* S        = g_S + (size_t)bh * SLQ * SLK;
    const int* mp   = mask + (size_t)b * SLQ * SLK;

    const int m0 = blockIdx.y * BM, n0 = blockIdx.x * BN;
    float acc[8][8] = {};
    gemm_tile<true>(Q + (size_t)m0 * DD, Kp + (size_t)n0 * DD, DD, DD, DD, acc, s);

    const float scale = 0.044194173824159216f;  // 1/sqrt(512)
    const int ty = threadIdx.x >> 4, tx = threadIdx.x & 15;
    #pragma unroll
    for (int i = 0; i < 8; i++) {
        const size_t off = (size_t)(m0 + ty*8 + i) * SLK + n0 + tx*8;
        int4 mk0 = *(const int4*)&mp[off];
        int4 mk1 = *(const int4*)&mp[off + 4];
        float4 v0, v1;
        v0.x = mk0.x ? acc[i][0]*scale : -1e30f;
        v0.y = mk0.y ? acc[i][1]*scale : -1e30f;
        v0.z = mk0.z ? acc[i][2]*scale : -1e30f;
        v0.w = mk0.w ? acc[i][3]*scale : -1e30f;
        v1.x = mk1.x ? acc[i][4]*scale : -1e30f;
        v1.y = mk1.y ? acc[i][5]*scale : -1e30f;
        v1.z = mk1.z ? acc[i][6]*scale : -1e30f;
        v1.w = mk1.w ? acc[i][7]*scale : -1e30f;
        *(float4*)&S[off]     = v0;
        *(float4*)&S[off + 4] = v1;
    }
}

// -------- Stage 3: row softmax over Lk=1024 (in place) --------
__global__ __launch_bounds__(256) void softmax_kernel()
{
    const size_t row = blockIdx.x;
    float* p = g_S + row * SLK;
    const int tid = threadIdx.x;
    const int wid = tid >> 5, lane = tid & 31;
    __shared__ float sred[8];

    float4 v = reinterpret_cast<float4*>(p)[tid];
    float m = fmaxf(fmaxf(v.x, v.y), fmaxf(v.z, v.w));
    #pragma unroll
    for (int o = 16; o; o >>= 1) m = fmaxf(m, __shfl_xor_sync(0xffffffffu, m, o));
    if (lane == 0) sred[wid] = m;
    __syncthreads();
    float rm = sred[0];
    #pragma unroll
    for (int i = 1; i < 8; i++) rm = fmaxf(rm, sred[i]);
    __syncthreads();

    v.x = __expf(v.x - rm);
    v.y = __expf(v.y - rm);
    v.z = __expf(v.z - rm);
    v.w = __expf(v.w - rm);
    float sum = (v.x + v.y) + (v.z + v.w);
    #pragma unroll
    for (int o = 16; o; o >>= 1) sum += __shfl_xor_sync(0xffffffffu, sum, o);
    if (lane == 0) sred[wid] = sum;
    __syncthreads();
    float tot = 0.f;
    #pragma unroll
    for (int i = 0; i < 8; i++) tot += sred[i];
    const float inv = 1.0f / tot;
    v.x *= inv; v.y *= inv; v.z *= inv; v.w *= inv;
    reinterpret_cast<float4*>(p)[tid] = v;
}

// -------- Stage 4: ctx = attn @ V (NN), written head-concatenated --------
__global__ __launch_bounds__(NTHREADS) void ctx_kernel()
{
    __shared__ Smem s;
    const int bh = blockIdx.z;
    const int b = bh >> 3, h = bh & 7;
    const float* P = g_S + (size_t)bh * SLQ * SLK;
    const float* V = g_V + (size_t)bh * SLK * DD;
    float* C = g_C + (size_t)b * SLQ * HD + (size_t)h * DD;

    const int m0 = blockIdx.y * BM, n0 = blockIdx.x * BN;
    float acc[8][8] = {};
    gemm_tile<false>(P + (size_t)m0 * SLK, V + n0, SLK, SLK, DD, acc, s);

    const int ty = threadIdx.x >> 4, tx = threadIdx.x & 15;
    #pragma unroll
    for (int i = 0; i < 8; i++) {
        const size_t off = (size_t)(m0 + ty*8 + i) * HD + n0 + tx*8;
        float4 o0, o1;
        o0.x = acc[i][0]; o0.y = acc[i][1]; o0.z = acc[i][2]; o0.w = acc[i][3];
        o1.x = acc[i][4]; o1.y = acc[i][5]; o1.z = acc[i][6]; o1.w = acc[i][7];
        *(float4*)&C[off]     = o0;
        *(float4*)&C[off + 4] = o1;
    }
}

// -------- Stage 5: out = ctx_concat @ Wp^T + bp --------
__global__ __launch_bounds__(NTHREADS) void proj_kernel(
    const float* __restrict__ Wp, const float* __restrict__ bp, float* __restrict__ out)
{
    __shared__ Smem s;
    const int m0 = blockIdx.y * BM, n0 = blockIdx.x * BN;
    float acc[8][8] = {};
    gemm_tile<true>(g_C + (size_t)m0 * HD, Wp + (size_t)n0 * HD, HD, HD, HD, acc, s);

    const int ty = threadIdx.x >> 4, tx = threadIdx.x & 15;
    float bj[8];
    *(float4*)&bj[0] = *(const float4*)&bp[n0 + tx*8];
    *(float4*)&bj[4] = *(const float4*)&bp[n0 + tx*8 + 4];
    #pragma unroll
    for (int i = 0; i < 8; i++) {
        const size_t off = (size_t)(m0 + ty*8 + i) * DD + n0 + tx*8;
        float4 o0, o1;
        o0.x = acc[i][0] + bj[0]; o0.y = acc[i][1] + bj[1];
        o0.z = acc[i][2] + bj[2]; o0.w = acc[i][3] + bj[3];
        o1.x = acc[i][4] + bj[4]; o1.y = acc[i][5] + bj[5];
        o1.z = acc[i][6] + bj[6]; o1.w = acc[i][7] + bj[7];
        *(float4*)&out[off]     = o0;
        *(float4*)&out[off + 4] = o1;
    }
}

extern "C" void kernel_launch(void* const* d_in, const int* in_sizes, int n_in,
                              void* d_out, int out_size)
{
    const float* x      = (const float*)d_in[0];
    const float* states = (const float*)d_in[1];
    const int*   mask   = (const int*)  d_in[2];
    const float* Wq     = (const float*)d_in[3];
    const float* bq     = (const float*)d_in[4];
    const float* Wk     = (const float*)d_in[5];
    const float* bk     = (const float*)d_in[6];
    const float* Wv     = (const float*)d_in[7];
    const float* bv     = (const float*)d_in[8];
    const float* Wp     = (const float*)d_in[9];
    const float* bp     = (const float*)d_in[10];
    float* out = (float*)d_out;

    dim3 blk(NTHREADS);
    // Stage 1: Q/K/V projections. N=512 -> 4 tiles, M=1024 -> 8 tiles, z = 3*64
    qkv_kernel<<<dim3(4, 8, 192), blk>>>(x, states, Wq, Wk, Wv, bq, bk, bv);
    // Stage 2: scores. N=1024 -> 8, M=1024 -> 8, z = 64
    scores_kernel<<<dim3(8, 8, 64), blk>>>(mask);
    // Stage 3: softmax over 65536 rows
    softmax_kernel<<<65536, 256>>>();
    // Stage 4: ctx. N=512 -> 4, M=1024 -> 8, z = 64
    ctx_kernel<<<dim3(4, 8, 64), blk>>>();
    // Stage 5: output projection. M=8192 -> 64, N=512 -> 4
    proj_kernel<<<dim3(4, 64, 1), blk>>>(Wp, bp, out);
}

// round 3
// speedup vs baseline: 2.6080x; 2.6080x over previous
#include <cuda_runtime.h>
#include <cuda_bf16.h>
#include <cstdint>

// Problem dims
#define NB 8
#define NH 8
#define SLQ 1024
#define SLK 1024
#define DD 512
#define HD 4096

using bf16 = __nv_bfloat16;

// ---------------- device global scratch ----------------
__device__ bf16 g_xh[(size_t)NB*SLQ*DD],  g_xl[(size_t)NB*SLQ*DD];
__device__ bf16 g_sh[(size_t)NB*SLK*DD],  g_sl[(size_t)NB*SLK*DD];
__device__ bf16 g_Wqh[(size_t)NH*DD*DD],  g_Wql[(size_t)NH*DD*DD];
__device__ bf16 g_Wkh[(size_t)NH*DD*DD],  g_Wkl[(size_t)NH*DD*DD];
__device__ bf16 g_Wvh[(size_t)NH*DD*DD],  g_Wvl[(size_t)NH*DD*DD];
__device__ bf16 g_Wph[(size_t)DD*HD],     g_Wpl[(size_t)DD*HD];
__device__ bf16 g_Qh[(size_t)64*SLQ*DD],  g_Ql[(size_t)64*SLQ*DD];
__device__ bf16 g_Kh[(size_t)64*SLK*DD],  g_Kl[(size_t)64*SLK*DD];
__device__ bf16 g_VTh[(size_t)64*DD*SLK], g_VTl[(size_t)64*DD*SLK];
__device__ float g_S[(size_t)64*SLQ*SLK];
__device__ bf16 g_Ph[(size_t)64*SLQ*SLK], g_Pl[(size_t)64*SLQ*SLK];
__device__ bf16 g_Ch[(size_t)NB*SLQ*HD],  g_Cl[(size_t)NB*SLQ*HD];

// ---------------- PTX helpers (baseline ISA only; no sm_103a-suffixed ops) ----------------
__device__ __forceinline__ uint32_t smem_u32(const void* p) {
    uint32_t a;
    asm("{ .reg .u64 t; cvta.to.shared.u64 t, %1; cvt.u32.u64 %0, t; }" : "=r"(a) : "l"(p));
    return a;
}
#define CP_ASYNC16(dst, src) \
    asm volatile("cp.async.cg.shared.global [%0], [%1], 16;" :: "r"(dst), "l"(src))
#define CP_COMMIT() asm volatile("cp.async.commit_group;" ::: "memory")
#define CP_WAIT1() asm volatile("cp.async.wait_group 1;" ::: "memory")
#define CP_WAIT0() asm volatile("cp.async.wait_group 0;" ::: "memory")

__device__ __forceinline__ void ldsm_x4(uint32_t* r, uint32_t addr) {
    asm volatile("ldmatrix.sync.aligned.m8n8.x4.shared.b16 {%0,%1,%2,%3}, [%4];"
        : "=r"(r[0]), "=r"(r[1]), "=r"(r[2]), "=r"(r[3]) : "r"(addr));
}
__device__ __forceinline__ void mma16816(float* d, const uint32_t* a, const uint32_t* b) {
    asm volatile("mma.sync.aligned.m16n8k16.row.col.f32.bf16.bf16.f32 "
        "{%0,%1,%2,%3}, {%4,%5,%6,%7}, {%8,%9}, {%0,%1,%2,%3};"
        : "+f"(d[0]), "+f"(d[1]), "+f"(d[2]), "+f"(d[3])
        : "r"(a[0]), "r"(a[1]), "r"(a[2]), "r"(a[3]), "r"(b[0]), "r"(b[1]));
}

// 64B-row swizzle: slot' = chunk ^ ((row>>1)&3), conflict-free for ldmatrix row groups
__device__ __forceinline__ uint32_t swzoff(int row, int chunk) {
    return (uint32_t)row * 64u + (uint32_t)((chunk ^ ((row >> 1) & 3)) << 4);
}

// SMEM: 2 stages x { Ah(8K), Al(8K), Bh(8K), Bl(8K) } = 64KB
#define TILE_B 8192
#define STAGE_B 32768
#define GEMM_SMEM 65536

// Epilogue IDs
#define EPI_QK  0  // bias + split hi/lo, row-major
#define EPI_VT  1  // bias + split hi/lo, transposed (write V^T)
#define EPI_SC  2  // scale + mask -> fp32
#define EPI_CTX 3  // split hi/lo, row-major (head-concat via oOff)
#define EPI_OUT 4  // bias -> fp32

template<int EPI>
__global__ void __launch_bounds__(256, 1) gemm3(
    const bf16* __restrict__ Ah, const bf16* __restrict__ Al, int lda,
    const bf16* __restrict__ Bh, const bf16* __restrict__ Bl, int ldb,
    int Ktot,
    const float* __restrict__ bias,
    const int* __restrict__ mask,
    float* __restrict__ outf,
    bf16* __restrict__ oh, bf16* __restrict__ ol, int ldo)
{
    extern __shared__ char smem[];
    const uint32_t sb = smem_u32(smem);
    const int tid = threadIdx.x;
    const int wid = tid >> 5;
    const int lane = tid & 31;
    const int z = blockIdx.z;
    const int m0 = blockIdx.y * 128;
    const int n0 = blockIdx.x * 128;

    size_t aOff = 0, bOff = 0, oOff = 0, mOff = 0;
    if (EPI == EPI_QK || EPI == EPI_VT) {
        aOff = (size_t)(z >> 3) * SLQ * DD;
        bOff = (size_t)(z & 7) * DD * DD;
        oOff = (EPI == EPI_QK) ? (size_t)z * SLQ * DD : (size_t)z * DD * SLK;
    } else if (EPI == EPI_SC) {
        aOff = (size_t)z * SLQ * DD;
        bOff = (size_t)z * SLK * DD;
        oOff = (size_t)z * SLQ * SLK;
        mOff = (size_t)(z >> 3) * SLQ * SLK;
    } else if (EPI == EPI_CTX) {
        aOff = (size_t)z * SLQ * SLK;
        bOff = (size_t)z * DD * SLK;
        oOff = (size_t)(z >> 3) * SLQ * HD + (size_t)(z & 7) * DD;
    }

    // ---- loader mapping: 4 tiles (Ah,Al,Bh,Bl) x 64 threads; 8 x 16B per thread per chunk
    const int tile = tid >> 6;
    const int t64  = tid & 63;
    const int lc   = t64 & 3;    // 16B chunk col (of 4 per 64B row)
    const int rb   = t64 >> 2;   // row base 0..15 (rows rb + 16i)
    const bf16* srcT;
    int ldT;
    if (tile == 0)      { srcT = Ah + aOff + (size_t)m0 * lda; ldT = lda; }
    else if (tile == 1) { srcT = Al + aOff + (size_t)m0 * lda; ldT = lda; }
    else if (tile == 2) { srcT = Bh + bOff + (size_t)n0 * ldb; ldT = ldb; }
    else                { srcT = Bl + bOff + (size_t)n0 * ldb; ldT = ldb; }
    srcT += (size_t)rb * ldT + lc * 8;

    uint32_t dstoff[8];
    #pragma unroll
    for (int i = 0; i < 8; i++)
        dstoff[i] = swzoff(rb + i * 16, lc);
    const uint32_t tbase0 = sb + tile * TILE_B;

    const int NCH = Ktot >> 5;  // BK = 32

    // prologue: chunk 0 -> stage 0
    {
        const bf16* s = srcT;
        #pragma unroll
        for (int i = 0; i < 8; i++)
            CP_ASYNC16(tbase0 + dstoff[i], s + (size_t)i * 16 * ldT);
        CP_COMMIT();
    }

    // ---- compute mapping
    const int warpM = wid & 3;       // 4 warps along M: 32 rows each
    const int warpN = wid >> 2;      // 2 warps along N: 64 cols each
    const int grp = lane >> 3;
    const int l7  = lane & 7;

    float acc[2][8][4];
    #pragma unroll
    for (int mt = 0; mt < 2; mt++)
        #pragma unroll
        for (int nt = 0; nt < 8; nt++)
            #pragma unroll
            for (int j = 0; j < 4; j++) acc[mt][nt][j] = 0.f;

    // A ldmatrix lane addr pieces: groups {m-lo/k-lo, m-hi/k-lo, m-lo/k-hi, m-hi/k-hi}
    const int arow = warpM * 32 + ((grp & 1) << 3) + l7;   // + mt*16
    const int achb = grp >> 1;                              // + ks*2
    // B ldmatrix: groups {n-lo/k-lo, n-lo/k-hi, n-hi/k-lo, n-hi/k-hi}
    const int brow = warpN * 64 + ((grp >> 1) << 3) + l7;  // + p*16
    const int bchb = grp & 1;                               // + ks*2

    for (int c = 0; c < NCH; c++) {
        if (c + 1 < NCH) {
            const uint32_t tb = tbase0 + ((c + 1) & 1) * STAGE_B;
            const bf16* s = srcT + (size_t)(c + 1) * 32;
            #pragma unroll
            for (int i = 0; i < 8; i++)
                CP_ASYNC16(tb + dstoff[i], s + (size_t)i * 16 * ldT);
            CP_COMMIT();
            CP_WAIT1();
        } else {
            CP_WAIT0();
        }
        __syncthreads();

        const uint32_t st = sb + (c & 1) * STAGE_B;
        #pragma unroll
        for (int ks = 0; ks < 2; ks++) {
            uint32_t ah[2][4], al[2][4], bh[4][4], bl[4][4];
            #pragma unroll
            for (int mt = 0; mt < 2; mt++) {
                const uint32_t off = swzoff(arow + mt * 16, achb + ks * 2);
                ldsm_x4(ah[mt], st + off);
                ldsm_x4(al[mt], st + TILE_B + off);
            }
            #pragma unroll
            for (int p = 0; p < 4; p++) {
                const uint32_t off = swzoff(brow + p * 16, bchb + ks * 2);
                ldsm_x4(bh[p], st + 2 * TILE_B + off);
                ldsm_x4(bl[p], st + 3 * TILE_B + off);
            }
            #pragma unroll
            for (int mt = 0; mt < 2; mt++) {
                #pragma unroll
                for (int p = 0; p < 4; p++) {
                    #pragma unroll
                    for (int h = 0; h < 2; h++) {
                        const int nt = p * 2 + h;
                        mma16816(acc[mt][nt], ah[mt], &bh[p][h * 2]);
                        mma16816(acc[mt][nt], ah[mt], &bl[p][h * 2]);
                        mma16816(acc[mt][nt], al[mt], &bh[p][h * 2]);
                    }
                }
            }
        }
        __syncthreads();
    }

    // ---------------- epilogue ----------------
    const int r4 = lane >> 2;
    const int c2 = (lane & 3) * 2;
    const int colb = n0 + warpN * 64 + c2;

    #pragma unroll
    for (int mt = 0; mt < 2; mt++) {
        #pragma unroll
        for (int rh = 0; rh < 2; rh++) {
            const int row = m0 + warpM * 32 + mt * 16 + rh * 8 + r4;
            if (EPI == EPI_QK || EPI == EPI_CTX) {
                const size_t rowbase = oOff + (size_t)row * ldo + colb;
                #pragma unroll
                for (int nt = 0; nt < 8; nt++) {
                    const int col = colb + nt * 8;
                    float v0 = acc[mt][nt][rh * 2 + 0];
                    float v1 = acc[mt][nt][rh * 2 + 1];
                    if (EPI == EPI_QK) { v0 += bias[col]; v1 += bias[col + 1]; }
                    bf16 h0 = __float2bfloat16(v0), h1 = __float2bfloat16(v1);
                    bf16 l0 = __float2bfloat16(v0 - __bfloat162float(h0));
                    bf16 l1 = __float2bfloat16(v1 - __bfloat162float(h1));
                    uint32_t ph = (uint32_t)*(unsigned short*)&h0 | ((uint32_t)*(unsigned short*)&h1 << 16);
                    uint32_t pl = (uint32_t)*(unsigned short*)&l0 | ((uint32_t)*(unsigned short*)&l1 << 16);
                    *(uint32_t*)(oh + rowbase + nt * 8) = ph;
                    *(uint32_t*)(ol + rowbase + nt * 8) = pl;
                }
            } else if (EPI == EPI_VT) {
                #pragma unroll
                for (int nt = 0; nt < 8; nt++) {
                    const int col = colb + nt * 8;
                    float v0 = acc[mt][nt][rh * 2 + 0] + bias[col];
                    float v1 = acc[mt][nt][rh * 2 + 1] + bias[col + 1];
                    bf16 h0 = __float2bfloat16(v0), h1 = __float2bfloat16(v1);
                    bf16 l0 = __float2bfloat16(v0 - __bfloat162float(h0));
                    bf16 l1 = __float2bfloat16(v1 - __bfloat162float(h1));
                    const size_t i0 = oOff + (size_t)col * SLK + row;
                    oh[i0] = h0; ol[i0] = l0;
                    oh[i0 + SLK] = h1; ol[i0 + SLK] = l1;
                }
            } else if (EPI == EPI_SC) {
                const float scale = 0.044194173824159216f;  // 1/sqrt(512)
                const size_t rowbase = oOff + (size_t)row * SLK + colb;
                const int* mp = mask + mOff + (size_t)row * SLK + colb;
                #pragma unroll
                for (int nt = 0; nt < 8; nt++) {
                    int2 mk = *(const int2*)(mp + nt * 8);
                    float2 o;
                    o.x = mk.x ? acc[mt][nt][rh * 2 + 0] * scale : -1e30f;
                    o.y = mk.y ? acc[mt][nt][rh * 2 + 1] * scale : -1e30f;
                    *(float2*)(outf + rowbase + nt * 8) = o;
                }
            } else {  // EPI_OUT
                const size_t rowbase = (size_t)row * ldo + colb;
                #pragma unroll
                for (int nt = 0; nt < 8; nt++) {
                    const int col = colb + nt * 8;
                    float2 o;
                    o.x = acc[mt][nt][rh * 2 + 0] + bias[col];
                    o.y = acc[mt][nt][rh * 2 + 1] + bias[col + 1];
                    *(float2*)(outf + rowbase + nt * 8) = o;
                }
            }
        }
    }
}

// ---------------- fp32 -> (hi, lo) bf16 conversion ----------------
__global__ void cvt4(const float* __restrict__ s, bf16* __restrict__ hi, bf16* __restrict__ lo, int n4)
{
    int i = blockIdx.x * blockDim.x + threadIdx.x;
    if (i >= n4) return;
    float4 v = ((const float4*)s)[i];
    bf16 h0 = __float2bfloat16(v.x), h1 = __float2bfloat16(v.y),
         h2 = __float2bfloat16(v.z), h3 = __float2bfloat16(v.w);
    bf16 l0 = __float2bfloat16(v.x - __bfloat162float(h0));
    bf16 l1 = __float2bfloat16(v.y - __bfloat162float(h1));
    bf16 l2 = __float2bfloat16(v.z - __bfloat162float(h2));
    bf16 l3 = __float2bfloat16(v.w - __bfloat162float(h3));
    uint2 vh, vl;
    unsigned short* ph = (unsigned short*)&vh;
    unsigned short* pl = (unsigned short*)&vl;
    ph[0] = *(unsigned short*)&h0; ph[1] = *(unsigned short*)&h1;
    ph[2] = *(unsigned short*)&h2; ph[3] = *(unsigned short*)&h3;
    pl[0] = *(unsigned short*)&l0; pl[1] = *(unsigned short*)&l1;
    pl[2] = *(unsigned short*)&l2; pl[3] = *(unsigned short*)&l3;
    ((uint2*)hi)[i] = vh;
    ((uint2*)lo)[i] = vl;
}

// ---------------- softmax over Lk=1024, emit hi/lo bf16 ----------------
__global__ void __launch_bounds__(256) softmax_hl()
{
    const size_t row = blockIdx.x;
    const float* p = g_S + row * SLK;
    bf16* ph = g_Ph + row * SLK;
    bf16* pl = g_Pl + row * SLK;
    const int tid = threadIdx.x;
    const int wid = tid >> 5, lane = tid & 31;
    __shared__ float sred[8];

    float4 v = ((const float4*)p)[tid];
    float m = fmaxf(fmaxf(v.x, v.y), fmaxf(v.z, v.w));
    #pragma unroll
    for (int o = 16; o; o >>= 1) m = fmaxf(m, __shfl_xor_sync(0xffffffffu, m, o));
    if (lane == 0) sred[wid] = m;
    __syncthreads();
    float rm = sred[0];
    #pragma unroll
    for (int i = 1; i < 8; i++) rm = fmaxf(rm, sred[i]);
    __syncthreads();

    v.x = __expf(v.x - rm); v.y = __expf(v.y - rm);
    v.z = __expf(v.z - rm); v.w = __expf(v.w - rm);
    float sum = (v.x + v.y) + (v.z + v.w);
    #pragma unroll
    for (int o = 16; o; o >>= 1) sum += __shfl_xor_sync(0xffffffffu, sum, o);
    if (lane == 0) sred[wid] = sum;
    __syncthreads();
    float tot = 0.f;
    #pragma unroll
    for (int i = 0; i < 8; i++) tot += sred[i];
    const float inv = 1.0f / tot;
    v.x *= inv; v.y *= inv; v.z *= inv; v.w *= inv;

    uint2 vh, vl;
    unsigned short* qh = (unsigned short*)&vh;
    unsigned short* ql = (unsigned short*)&vl;
    float vv[4] = {v.x, v.y, v.z, v.w};
    #pragma unroll
    for (int j = 0; j < 4; j++) {
        bf16 h = __float2bfloat16(vv[j]);
        bf16 l = __float2bfloat16(vv[j] - __bfloat162float(h));
        qh[j] = *(unsigned short*)&h;
        ql[j] = *(unsigned short*)&l;
    }
    ((uint2*)ph)[tid] = vh;
    ((uint2*)pl)[tid] = vl;
}

// ---------------- host launch ----------------
template<typename T>
static T* symaddr(const void* sym) {
    void* p = nullptr;
    cudaGetSymbolAddress(&p, sym);
    return (T*)p;
}

extern "C" void kernel_launch(void* const* d_in, const int* in_sizes, int n_in,
                              void* d_out, int out_size)
{
    const float* x      = (const float*)d_in[0];
    const float* states = (const float*)d_in[1];
    const int*   mask   = (const int*)  d_in[2];
    const float* Wq     = (const float*)d_in[3];
    const float* bq     = (const float*)d_in[4];
    const float* Wk     = (const float*)d_in[5];
    const float* bk     = (const float*)d_in[6];
    const float* Wv     = (const float*)d_in[7];
    const float* bv     = (const float*)d_in[8];
    const float* Wp     = (const float*)d_in[9];
    const float* bp     = (const float*)d_in[10];
    float* out = (float*)d_out;

    bf16 *xh = symaddr<bf16>(g_xh), *xl = symaddr<bf16>(g_xl);
    bf16 *sh = symaddr<bf16>(g_sh), *sl = symaddr<bf16>(g_sl);
    bf16 *wqh = symaddr<bf16>(g_Wqh), *wql = symaddr<bf16>(g_Wql);
    bf16 *wkh = symaddr<bf16>(g_Wkh), *wkl = symaddr<bf16>(g_Wkl);
    bf16 *wvh = symaddr<bf16>(g_Wvh), *wvl = symaddr<bf16>(g_Wvl);
    bf16 *wph = symaddr<bf16>(g_Wph), *wpl = symaddr<bf16>(g_Wpl);
    bf16 *qhh = symaddr<bf16>(g_Qh), *qll = symaddr<bf16>(g_Ql);
    bf16 *khh = symaddr<bf16>(g_Kh), *kll = symaddr<bf16>(g_Kl);
    bf16 *vth = symaddr<bf16>(g_VTh), *vtl = symaddr<bf16>(g_VTl);
    float *Sf = symaddr<float>(g_S);
    bf16 *phh = symaddr<bf16>(g_Ph), *pll = symaddr<bf16>(g_Pl);
    bf16 *chh = symaddr<bf16>(g_Ch), *cll = symaddr<bf16>(g_Cl);

    static bool attr_done = false;
    if (!attr_done) {
        cudaFuncSetAttribute(gemm3<EPI_QK>,  cudaFuncAttributeMaxDynamicSharedMemorySize, GEMM_SMEM);
        cudaFuncSetAttribute(gemm3<EPI_VT>,  cudaFuncAttributeMaxDynamicSharedMemorySize, GEMM_SMEM);
        cudaFuncSetAttribute(gemm3<EPI_SC>,  cudaFuncAttributeMaxDynamicSharedMemorySize, GEMM_SMEM);
        cudaFuncSetAttribute(gemm3<EPI_CTX>, cudaFuncAttributeMaxDynamicSharedMemorySize, GEMM_SMEM);
        cudaFuncSetAttribute(gemm3<EPI_OUT>, cudaFuncAttributeMaxDynamicSharedMemorySize, GEMM_SMEM);
        attr_done = true;
    }

    // Conversions
    auto cvl = [&](const float* src, bf16* hi, bf16* lo, size_t n) {
        int n4 = (int)(n / 4);
        cvt4<<<(n4 + 255) / 256, 256>>>(src, hi, lo, n4);
    };
    cvl(x,      xh, xl,  (size_t)NB * SLQ * DD);
    cvl(states, sh, sl,  (size_t)NB * SLK * DD);
    cvl(Wq,     wqh, wql, (size_t)NH * DD * DD);
    cvl(Wk,     wkh, wkl, (size_t)NH * DD * DD);
    cvl(Wv,     wvh, wvl, (size_t)NH * DD * DD);
    cvl(Wp,     wph, wpl, (size_t)DD * HD);

    // Stage 1: projections (M=1024, N=512, K=512) x 64 (b,h)
    gemm3<EPI_QK><<<dim3(4, 8, 64), 256, GEMM_SMEM>>>(
        xh, xl, DD, wqh, wql, DD, DD, bq, nullptr, nullptr, qhh, qll, DD);
    gemm3<EPI_QK><<<dim3(4, 8, 64), 256, GEMM_SMEM>>>(
        sh, sl, DD, wkh, wkl, DD, DD, bk, nullptr, nullptr, khh, kll, DD);
    gemm3<EPI_VT><<<dim3(4, 8, 64), 256, GEMM_SMEM>>>(
        sh, sl, DD, wvh, wvl, DD, DD, bv, nullptr, nullptr, vth, vtl, SLK);

    // Stage 2: scores = Q K^T * scale, masked (M=1024, N=1024, K=512)
    gemm3<EPI_SC><<<dim3(8, 8, 64), 256, GEMM_SMEM>>>(
        qhh, qll, DD, khh, kll, DD, DD, nullptr, mask, Sf, nullptr, nullptr, SLK);

    // Stage 3: softmax + split
    softmax_hl<<<65536, 256>>>();

    // Stage 4: ctx = P V^T-form (M=1024, N=512, K=1024), head-concat epilogue
    gemm3<EPI_CTX><<<dim3(4, 8, 64), 256, GEMM_SMEM>>>(
        phh, pll, SLK, vth, vtl, SLK, SLK, nullptr, nullptr, nullptr, chh, cll, HD);

    // Stage 5: out = C Wp^T + bp (M=8192, N=512, K=4096)
    gemm3<EPI_OUT><<<dim3(4, 64, 1), 256, GEMM_SMEM>>>(
        chh, cll, HD, wph, wpl, HD, HD, bp, nullptr, out, nullptr, nullptr, DD);
}

// round 4
// speedup vs baseline: 2.8968x; 1.1107x over previous
#include <cuda_runtime.h>
#include <cuda_bf16.h>
#include <cstdint>

// Problem dims
#define NB 8
#define NH 8
#define SLQ 1024
#define SLK 1024
#define DD 512
#define HD 4096

using bf16 = __nv_bfloat16;

// ---------------- device global scratch ----------------
__device__ bf16 g_xh[(size_t)NB*SLQ*DD],  g_xl[(size_t)NB*SLQ*DD];
__device__ bf16 g_sh[(size_t)NB*SLK*DD],  g_sl[(size_t)NB*SLK*DD];
__device__ bf16 g_Wqh[(size_t)NH*DD*DD],  g_Wql[(size_t)NH*DD*DD];
__device__ bf16 g_Wkh[(size_t)NH*DD*DD],  g_Wkl[(size_t)NH*DD*DD];
__device__ bf16 g_Wvh[(size_t)NH*DD*DD],  g_Wvl[(size_t)NH*DD*DD];
__device__ bf16 g_Wph[(size_t)DD*HD],     g_Wpl[(size_t)DD*HD];
__device__ bf16 g_QKh[(size_t)128*SLQ*DD], g_QKl[(size_t)128*SLQ*DD];  // Q: z<64, K: z>=64
__device__ bf16 g_VTh[(size_t)64*DD*SLK],  g_VTl[(size_t)64*DD*SLK];
__device__ float g_S[(size_t)64*SLQ*SLK];
__device__ bf16 g_Ph[(size_t)64*SLQ*SLK], g_Pl[(size_t)64*SLQ*SLK];
__device__ bf16 g_Ch[(size_t)NB*SLQ*HD],  g_Cl[(size_t)NB*SLQ*HD];

// ---------------- PTX helpers (baseline ISA only) ----------------
__device__ __forceinline__ uint32_t smem_u32(const void* p) {
    uint32_t a;
    asm("{ .reg .u64 t; cvta.to.shared.u64 t, %1; cvt.u32.u64 %0, t; }" : "=r"(a) : "l"(p));
    return a;
}
#define CP_ASYNC16(dst, src) \
    asm volatile("cp.async.cg.shared.global [%0], [%1], 16;" :: "r"(dst), "l"(src))
#define CP_COMMIT() asm volatile("cp.async.commit_group;" ::: "memory")
#define CP_WAIT1() asm volatile("cp.async.wait_group 1;" ::: "memory")
#define CP_WAIT0() asm volatile("cp.async.wait_group 0;" ::: "memory")

__device__ __forceinline__ void ldsm_x4(uint32_t* r, uint32_t addr) {
    asm volatile("ldmatrix.sync.aligned.m8n8.x4.shared.b16 {%0,%1,%2,%3}, [%4];"
        : "=r"(r[0]), "=r"(r[1]), "=r"(r[2]), "=r"(r[3]) : "r"(addr));
}
__device__ __forceinline__ void mma16816(float* d, const uint32_t* a, const uint32_t* b) {
    asm volatile("mma.sync.aligned.m16n8k16.row.col.f32.bf16.bf16.f32 "
        "{%0,%1,%2,%3}, {%4,%5,%6,%7}, {%8,%9}, {%0,%1,%2,%3};"
        : "+f"(d[0]), "+f"(d[1]), "+f"(d[2]), "+f"(d[3])
        : "r"(a[0]), "r"(a[1]), "r"(a[2]), "r"(a[3]), "r"(b[0]), "r"(b[1]));
}

// 64B-row swizzle: slot' = chunk ^ ((row>>1)&3), conflict-free for ldmatrix groups
__device__ __forceinline__ uint32_t swzoff(int row, int chunk) {
    return (uint32_t)row * 64u + (uint32_t)((chunk ^ ((row >> 1) & 3)) << 4);
}

// Tiles: CTA 256(M) x 128(N) x 32(K); warps 4x2 of 64x64
// SMEM stage: Ah 16K | Al 16K | Bh 8K | Bl 8K = 48KB; 2 stages = 96KB
#define OFF_AL 16384
#define OFF_BH 32768
#define OFF_BL 40960
#define STAGE_B 49152
#define GEMM_SMEM 98304

// Epilogue IDs
#define EPI_QK  0  // dual-source (z>>6 selects), bias + split hi/lo, row-major
#define EPI_VT  1  // bias + split hi/lo, transposed (write V^T)
#define EPI_SC  2  // scale + mask -> fp32
#define EPI_CTX 3  // split hi/lo, row-major (head-concat via oOff)
#define EPI_OUT 4  // bias -> fp32

template<int EPI>
__global__ void __launch_bounds__(256, 1) gemm3(
    const bf16* __restrict__ Ah, const bf16* __restrict__ Al,
    const bf16* __restrict__ A2h, const bf16* __restrict__ A2l, int lda,
    const bf16* __restrict__ Bh, const bf16* __restrict__ Bl,
    const bf16* __restrict__ B2h, const bf16* __restrict__ B2l, int ldb,
    int Ktot,
    const float* __restrict__ bias, const float* __restrict__ bias2,
    const int* __restrict__ mask,
    float* __restrict__ outf,
    bf16* __restrict__ oh, bf16* __restrict__ ol, int ldo)
{
    extern __shared__ char smem[];
    const uint32_t sb = smem_u32(smem);
    const int tid = threadIdx.x;
    const int wid = tid >> 5;
    const int lane = tid & 31;
    const int z = blockIdx.z;
    const int m0 = blockIdx.y * 256;
    const int n0 = blockIdx.x * 128;

    size_t aOff = 0, bOff = 0, oOff = 0, mOff = 0;
    if (EPI == EPI_QK) {
        const int zz = z & 63;
        if (z >= 64) { Ah = A2h; Al = A2l; Bh = B2h; Bl = B2l; bias = bias2; }
        aOff = (size_t)(zz >> 3) * SLQ * DD;
        bOff = (size_t)(zz & 7) * DD * DD;
        oOff = (size_t)z * SLQ * DD;
    } else if (EPI == EPI_VT) {
        aOff = (size_t)(z >> 3) * SLQ * DD;
        bOff = (size_t)(z & 7) * DD * DD;
        oOff = (size_t)z * DD * SLK;
    } else if (EPI == EPI_SC) {
        aOff = (size_t)z * SLQ * DD;
        bOff = (size_t)z * SLK * DD;
        oOff = (size_t)z * SLQ * SLK;
        mOff = (size_t)(z >> 3) * SLQ * SLK;
    } else if (EPI == EPI_CTX) {
        aOff = (size_t)z * SLQ * SLK;
        bOff = (size_t)z * DD * SLK;
        oOff = (size_t)(z >> 3) * SLQ * HD + (size_t)(z & 7) * DD;
    }

    // ---- loader mapping: 256 threads; A: 4 rows-passes, B: 2
    const int lc = tid & 3;     // 16B k-chunk (0..3)
    const int lr = tid >> 2;    // row 0..63
    uint32_t soff[4];
    #pragma unroll
    for (int i = 0; i < 4; i++)
        soff[i] = swzoff(lr + 64 * i, lc);
    const bf16* sAh = Ah + aOff + (size_t)(m0 + lr) * lda + lc * 8;
    const bf16* sAl = Al + aOff + (size_t)(m0 + lr) * lda + lc * 8;
    const bf16* sBh = Bh + bOff + (size_t)(n0 + lr) * ldb + lc * 8;
    const bf16* sBl = Bl + bOff + (size_t)(n0 + lr) * ldb + lc * 8;

    const int NCH = Ktot >> 5;  // BK = 32

#define LOAD_CHUNK(stg, kt) do { \
    const uint32_t _b = sb + (stg) * STAGE_B; \
    _Pragma("unroll") \
    for (int i = 0; i < 4; i++) CP_ASYNC16(_b + soff[i],          sAh + (kt) + (size_t)(64 * i) * lda); \
    _Pragma("unroll") \
    for (int i = 0; i < 4; i++) CP_ASYNC16(_b + OFF_AL + soff[i], sAl + (kt) + (size_t)(64 * i) * lda); \
    _Pragma("unroll") \
    for (int i = 0; i < 2; i++) CP_ASYNC16(_b + OFF_BH + soff[i], sBh + (kt) + (size_t)(64 * i) * ldb); \
    _Pragma("unroll") \
    for (int i = 0; i < 2; i++) CP_ASYNC16(_b + OFF_BL + soff[i], sBl + (kt) + (size_t)(64 * i) * ldb); \
    CP_COMMIT(); } while (0)

    LOAD_CHUNK(0, 0);

    // ---- compute mapping: warp grid 4(M) x 2(N), warp tile 64x64
    const int warpM = wid >> 1;
    const int warpN = wid & 1;
    const int grp = lane >> 3;
    const int l7  = lane & 7;
    const int arowb = warpM * 64 + ((grp & 1) << 3) + l7;   // + mt*16
    const int achb  = grp >> 1;                              // + ks*2
    const int browb = warpN * 64 + ((grp >> 1) << 3) + l7;  // + p*16
    const int bchb  = grp & 1;                               // + ks*2

    float acc[4][8][4];
    #pragma unroll
    for (int mt = 0; mt < 4; mt++)
        #pragma unroll
        for (int nt = 0; nt < 8; nt++)
            #pragma unroll
            for (int j = 0; j < 4; j++) acc[mt][nt][j] = 0.f;

    for (int c = 0; c < NCH; c++) {
        if (c + 1 < NCH) {
            LOAD_CHUNK((c + 1) & 1, (size_t)(c + 1) * 32);
            CP_WAIT1();
        } else {
            CP_WAIT0();
        }
        __syncthreads();

        const uint32_t st = sb + (c & 1) * STAGE_B;
        #pragma unroll
        for (int ks = 0; ks < 2; ks++) {
            uint32_t ah[4][4], al[4][4];
            #pragma unroll
            for (int mt = 0; mt < 4; mt++) {
                const uint32_t off = swzoff(arowb + mt * 16, achb + ks * 2);
                ldsm_x4(ah[mt], st + off);
                ldsm_x4(al[mt], st + OFF_AL + off);
            }
            #pragma unroll
            for (int p = 0; p < 4; p++) {
                uint32_t bh[4], bl[4];
                const uint32_t off = swzoff(browb + p * 16, bchb + ks * 2);
                ldsm_x4(bh, st + OFF_BH + off);
                ldsm_x4(bl, st + OFF_BL + off);
                #pragma unroll
                for (int mt = 0; mt < 4; mt++) {
                    #pragma unroll
                    for (int h = 0; h < 2; h++) {
                        const int nt = p * 2 + h;
                        mma16816(acc[mt][nt], ah[mt], &bh[h * 2]);
                        mma16816(acc[mt][nt], ah[mt], &bl[h * 2]);
                        mma16816(acc[mt][nt], al[mt], &bh[h * 2]);
                    }
                }
            }
        }
        __syncthreads();
    }

    // ---------------- epilogue ----------------
    const int r4 = lane >> 2;
    const int c2 = (lane & 3) * 2;
    const int colb = n0 + warpN * 64 + c2;

    #pragma unroll
    for (int mt = 0; mt < 4; mt++) {
        #pragma unroll
        for (int rh = 0; rh < 2; rh++) {
            const int row = m0 + warpM * 64 + mt * 16 + rh * 8 + r4;
            if (EPI == EPI_QK || EPI == EPI_CTX) {
                const size_t rowbase = oOff + (size_t)row * ldo + colb;
                #pragma unroll
                for (int nt = 0; nt < 8; nt++) {
                    const int col = colb + nt * 8;
                    float v0 = acc[mt][nt][rh * 2 + 0];
                    float v1 = acc[mt][nt][rh * 2 + 1];
                    if (EPI == EPI_QK) { v0 += bias[col]; v1 += bias[col + 1]; }
                    bf16 h0 = __float2bfloat16(v0), h1 = __float2bfloat16(v1);
                    bf16 l0 = __float2bfloat16(v0 - __bfloat162float(h0));
                    bf16 l1 = __float2bfloat16(v1 - __bfloat162float(h1));
                    uint32_t ph = (uint32_t)*(unsigned short*)&h0 | ((uint32_t)*(unsigned short*)&h1 << 16);
                    uint32_t pl = (uint32_t)*(unsigned short*)&l0 | ((uint32_t)*(unsigned short*)&l1 << 16);
                    *(uint32_t*)(oh + rowbase + nt * 8) = ph;
                    *(uint32_t*)(ol + rowbase + nt * 8) = pl;
                }
            } else if (EPI == EPI_VT) {
                #pragma unroll
                for (int nt = 0; nt < 8; nt++) {
                    const int col = colb + nt * 8;
                    float v0 = acc[mt][nt][rh * 2 + 0] + bias[col];
                    float v1 = acc[mt][nt][rh * 2 + 1] + bias[col + 1];
                    bf16 h0 = __float2bfloat16(v0), h1 = __float2bfloat16(v1);
                    bf16 l0 = __float2bfloat16(v0 - __bfloat162float(h0));
                    bf16 l1 = __float2bfloat16(v1 - __bfloat162float(h1));
                    const size_t i0 = oOff + (size_t)col * SLK + row;
                    oh[i0] = h0; ol[i0] = l0;
                    oh[i0 + SLK] = h1; ol[i0 + SLK] = l1;
                }
            } else if (EPI == EPI_SC) {
                const float scale = 0.044194173824159216f;  // 1/sqrt(512)
                const size_t rowbase = oOff + (size_t)row * SLK + colb;
                const int* mp = mask + mOff + (size_t)row * SLK + colb;
                #pragma unroll
                for (int nt = 0; nt < 8; nt++) {
                    int2 mk = *(const int2*)(mp + nt * 8);
                    float2 o;
                    o.x = mk.x ? acc[mt][nt][rh * 2 + 0] * scale : -1e30f;
                    o.y = mk.y ? acc[mt][nt][rh * 2 + 1] * scale : -1e30f;
                    *(float2*)(outf + rowbase + nt * 8) = o;
                }
            } else {  // EPI_OUT
                const size_t rowbase = (size_t)row * ldo + colb;
                #pragma unroll
                for (int nt = 0; nt < 8; nt++) {
                    const int col = colb + nt * 8;
                    float2 o;
                    o.x = acc[mt][nt][rh * 2 + 0] + bias[col];
                    o.y = acc[mt][nt][rh * 2 + 1] + bias[col + 1];
                    *(float2*)(outf + rowbase + nt * 8) = o;
                }
            }
        }
    }
}

// ---------------- fused fp32 -> (hi, lo) bf16 conversion ----------------
__global__ void cvt_all(
    const float* __restrict__ x, const float* __restrict__ st,
    const float* __restrict__ wq, const float* __restrict__ wk,
    const float* __restrict__ wv, const float* __restrict__ wp,
    bf16* xh, bf16* xl, bf16* shh, bf16* sll,
    bf16* wqh, bf16* wql, bf16* wkh, bf16* wkl,
    bf16* wvh, bf16* wvl, bf16* wph, bf16* wpl)
{
    const int which = blockIdx.y;
    const float* s; bf16 *hi, *lo; int n4;
    if (which == 0)      { s = x;  hi = xh;  lo = xl;  n4 = NB*SLQ*DD/4; }
    else if (which == 1) { s = st; hi = shh; lo = sll; n4 = NB*SLK*DD/4; }
    else if (which == 2) { s = wq; hi = wqh; lo = wql; n4 = NH*DD*DD/4; }
    else if (which == 3) { s = wk; hi = wkh; lo = wkl; n4 = NH*DD*DD/4; }
    else if (which == 4) { s = wv; hi = wvh; lo = wvl; n4 = NH*DD*DD/4; }
    else                 { s = wp; hi = wph; lo = wpl; n4 = DD*HD/4; }
    int i = blockIdx.x * blockDim.x + threadIdx.x;
    if (i >= n4) return;
    float4 v = ((const float4*)s)[i];
    bf16 h0 = __float2bfloat16(v.x), h1 = __float2bfloat16(v.y),
         h2 = __float2bfloat16(v.z), h3 = __float2bfloat16(v.w);
    bf16 l0 = __float2bfloat16(v.x - __bfloat162float(h0));
    bf16 l1 = __float2bfloat16(v.y - __bfloat162float(h1));
    bf16 l2 = __float2bfloat16(v.z - __bfloat162float(h2));
    bf16 l3 = __float2bfloat16(v.w - __bfloat162float(h3));
    uint2 vh, vl;
    unsigned short* ph = (unsigned short*)&vh;
    unsigned short* pl = (unsigned short*)&vl;
    ph[0] = *(unsigned short*)&h0; ph[1] = *(unsigned short*)&h1;
    ph[2] = *(unsigned short*)&h2; ph[3] = *(unsigned short*)&h3;
    pl[0] = *(unsigned short*)&l0; pl[1] = *(unsigned short*)&l1;
    pl[2] = *(unsigned short*)&l2; pl[3] = *(unsigned short*)&l3;
    ((uint2*)hi)[i] = vh;
    ((uint2*)lo)[i] = vl;
}

// ---------------- softmax over Lk=1024, emit hi/lo bf16 ----------------
__global__ void __launch_bounds__(256) softmax_hl()
{
    const size_t row = blockIdx.x;
    const float* p = g_S + row * SLK;
    bf16* ph = g_Ph + row * SLK;
    bf16* pl = g_Pl + row * SLK;
    const int tid = threadIdx.x;
    const int wid = tid >> 5, lane = tid & 31;
    __shared__ float sred[8];

    float4 v = ((const float4*)p)[tid];
    float m = fmaxf(fmaxf(v.x, v.y), fmaxf(v.z, v.w));
    #pragma unroll
    for (int o = 16; o; o >>= 1) m = fmaxf(m, __shfl_xor_sync(0xffffffffu, m, o));
    if (lane == 0) sred[wid] = m;
    __syncthreads();
    float rm = sred[0];
    #pragma unroll
    for (int i = 1; i < 8; i++) rm = fmaxf(rm, sred[i]);
    __syncthreads();

    v.x = __expf(v.x - rm); v.y = __expf(v.y - rm);
    v.z = __expf(v.z - rm); v.w = __expf(v.w - rm);
    float sum = (v.x + v.y) + (v.z + v.w);
    #pragma unroll
    for (int o = 16; o; o >>= 1) sum += __shfl_xor_sync(0xffffffffu, sum, o);
    if (lane == 0) sred[wid] = sum;
    __syncthreads();
    float tot = 0.f;
    #pragma unroll
    for (int i = 0; i < 8; i++) tot += sred[i];
    const float inv = 1.0f / tot;
    v.x *= inv; v.y *= inv; v.z *= inv; v.w *= inv;

    uint2 vh, vl;
    unsigned short* qh = (unsigned short*)&vh;
    unsigned short* ql = (unsigned short*)&vl;
    float vv[4] = {v.x, v.y, v.z, v.w};
    #pragma unroll
    for (int j = 0; j < 4; j++) {
        bf16 h = __float2bfloat16(vv[j]);
        bf16 l = __float2bfloat16(vv[j] - __bfloat162float(h));
        qh[j] = *(unsigned short*)&h;
        ql[j] = *(unsigned short*)&l;
    }
    ((uint2*)ph)[tid] = vh;
    ((uint2*)pl)[tid] = vl;
}

// ---------------- host launch ----------------
template<typename T>
static T* symaddr(const void* sym) {
    void* p = nullptr;
    cudaGetSymbolAddress(&p, sym);
    return (T*)p;
}

extern "C" void kernel_launch(void* const* d_in, const int* in_sizes, int n_in,
                              void* d_out, int out_size)
{
    const float* x      = (const float*)d_in[0];
    const float* states = (const float*)d_in[1];
    const int*   mask   = (const int*)  d_in[2];
    const float* Wq     = (const float*)d_in[3];
    const float* bq     = (const float*)d_in[4];
    const float* Wk     = (const float*)d_in[5];
    const float* bk     = (const float*)d_in[6];
    const float* Wv     = (const float*)d_in[7];
    const float* bv     = (const float*)d_in[8];
    const float* Wp     = (const float*)d_in[9];
    const float* bp     = (const float*)d_in[10];
    float* out = (float*)d_out;

    bf16 *xh = symaddr<bf16>(g_xh), *xl = symaddr<bf16>(g_xl);
    bf16 *sh = symaddr<bf16>(g_sh), *sl = symaddr<bf16>(g_sl);
    bf16 *wqh = symaddr<bf16>(g_Wqh), *wql = symaddr<bf16>(g_Wql);
    bf16 *wkh = symaddr<bf16>(g_Wkh), *wkl = symaddr<bf16>(g_Wkl);
    bf16 *wvh = symaddr<bf16>(g_Wvh), *wvl = symaddr<bf16>(g_Wvl);
    bf16 *wph = symaddr<bf16>(g_Wph), *wpl = symaddr<bf16>(g_Wpl);
    bf16 *qkh = symaddr<bf16>(g_QKh), *qkl = symaddr<bf16>(g_QKl);
    bf16 *vth = symaddr<bf16>(g_VTh), *vtl = symaddr<bf16>(g_VTl);
    float *Sf = symaddr<float>(g_S);
    bf16 *phh = symaddr<bf16>(g_Ph), *pll = symaddr<bf16>(g_Pl);
    bf16 *chh = symaddr<bf16>(g_Ch), *cll = symaddr<bf16>(g_Cl);

    cudaFuncSetAttribute(gemm3<EPI_QK>,  cudaFuncAttributeMaxDynamicSharedMemorySize, GEMM_SMEM);
    cudaFuncSetAttribute(gemm3<EPI_VT>,  cudaFuncAttributeMaxDynamicSharedMemorySize, GEMM_SMEM);
    cudaFuncSetAttribute(gemm3<EPI_SC>,  cudaFuncAttributeMaxDynamicSharedMemorySize, GEMM_SMEM);
    cudaFuncSetAttribute(gemm3<EPI_CTX>, cudaFuncAttributeMaxDynamicSharedMemorySize, GEMM_SMEM);
    cudaFuncSetAttribute(gemm3<EPI_OUT>, cudaFuncAttributeMaxDynamicSharedMemorySize, GEMM_SMEM);

    // Launch 0: all conversions in one grid
    cvt_all<<<dim3(4096, 6), 256>>>(x, states, Wq, Wk, Wv, Wp,
        xh, xl, sh, sl, wqh, wql, wkh, wkl, wvh, wvl, wph, wpl);

    // Launch 1: Q (z<64) and K (z>=64) projections, M=1024 N=512 K=512
    gemm3<EPI_QK><<<dim3(4, 4, 128), 256, GEMM_SMEM>>>(
        xh, xl, sh, sl, DD, wqh, wql, wkh, wkl, DD, DD,
        bq, bk, nullptr, nullptr, qkh, qkl, DD);

    // Launch 2: V projection -> V^T
    gemm3<EPI_VT><<<dim3(4, 4, 64), 256, GEMM_SMEM>>>(
        sh, sl, nullptr, nullptr, DD, wvh, wvl, nullptr, nullptr, DD, DD,
        bv, nullptr, nullptr, nullptr, vth, vtl, SLK);

    // Launch 3: scores = Q K^T * scale, masked (M=1024, N=1024, K=512)
    gemm3<EPI_SC><<<dim3(8, 4, 64), 256, GEMM_SMEM>>>(
        qkh, qkl, nullptr, nullptr, DD,
        qkh + (size_t)64 * SLQ * DD, qkl + (size_t)64 * SLQ * DD, nullptr, nullptr, DD, DD,
        nullptr, nullptr, mask, Sf, nullptr, nullptr, SLK);

    // Launch 4: softmax + split
    softmax_hl<<<65536, 256>>>();

    // Launch 5 (profiled): ctx = P V^T-form (M=1024, N=512, K=1024)
    gemm3<EPI_CTX><<<dim3(4, 4, 64), 256, GEMM_SMEM>>>(
        phh, pll, nullptr, nullptr, SLK, vth, vtl, nullptr, nullptr, SLK, SLK,
        nullptr, nullptr, nullptr, nullptr, chh, cll, HD);

    // Launch 6: out = C Wp^T + bp (M=8192, N=512, K=4096)
    gemm3<EPI_OUT><<<dim3(4, 32, 1), 256, GEMM_SMEM>>>(
        chh, cll, nullptr, nullptr, HD, wph, wpl, nullptr, nullptr, HD, HD,
        bp, nullptr, nullptr, out, nullptr, nullptr, DD);
}